// round 4
// baseline (speedup 1.0000x reference)
#include <cuda_runtime.h>
#include <math.h>

// Problem constants
#define Tn 8192          // B*S tokens
#define Dd 1024          // model dim
#define Ii 4096          // ffn dim
#define Ee 8             // experts
#define NROWS 16384      // Tn * top_k
#define NROWS_PAD (NROWS + 128)

// ---------------- scratch (__device__ globals; alloc-free) ----------------
__device__ float d_xp[(size_t)NROWS_PAD * Dd];   // permuted x rows (by expert)
__device__ float d_h [(size_t)NROWS_PAD * Ii];   // gelu(x@W1+b1)
__device__ float d_y [(size_t)NROWS * Dd];       // h@W2+b2
__device__ int   d_cnt[Ee];
__device__ int   d_off[Ee];
__device__ int   d_expert[NROWS];
__device__ int   d_pos[NROWS];
__device__ int   d_rowof[NROWS];
__device__ float d_gatev[NROWS];

// ---------------- small helpers ----------------
__device__ __forceinline__ unsigned f2tf32(float f){
  unsigned u; asm volatile("cvt.rna.tf32.f32 %0, %1;\n" : "=r"(u) : "f"(f)); return u;
}
__device__ __forceinline__ void cp16(void* smem_dst, const void* gmem_src){
  unsigned d = (unsigned)__cvta_generic_to_shared(smem_dst);
  asm volatile("cp.async.cg.shared.global [%0], [%1], 16;\n" :: "r"(d), "l"(gmem_src));
}
__device__ __forceinline__ void cp_commit(){ asm volatile("cp.async.commit_group;\n"); }
__device__ __forceinline__ void cp_wait1(){ asm volatile("cp.async.wait_group 1;\n"); }
__device__ __forceinline__ void cp_wait0(){ asm volatile("cp.async.wait_group 0;\n"); }

__device__ __forceinline__ void mma_tf32(float* d, const unsigned* a, const unsigned* b){
  asm volatile(
    "mma.sync.aligned.m16n8k8.row.col.f32.tf32.tf32.f32 "
    "{%0,%1,%2,%3}, {%4,%5,%6,%7}, {%8,%9}, {%0,%1,%2,%3};\n"
    : "+f"(d[0]), "+f"(d[1]), "+f"(d[2]), "+f"(d[3])
    : "r"(a[0]), "r"(a[1]), "r"(a[2]), "r"(a[3]), "r"(b[0]), "r"(b[1]));
}

__device__ __forceinline__ float gelu_exact(float v){
  return v * 0.5f * (1.0f + erff(v * 0.70710678118654752f));
}

// ---------------- router ----------------
__global__ void zero_cnt_kernel(){ if (threadIdx.x < Ee) d_cnt[threadIdx.x] = 0; }

__global__ void router_kernel(const float* __restrict__ x, const float* __restrict__ Wr,
                              const float* __restrict__ br){
  int t = (blockIdx.x * blockDim.x + threadIdx.x) >> 5;
  int lane = threadIdx.x & 31;
  if (t >= Tn) return;
  const float4* xr = (const float4*)(x + (size_t)t * Dd);
  float acc[Ee];
  #pragma unroll
  for (int e = 0; e < Ee; e++) acc[e] = 0.f;
  #pragma unroll
  for (int i = lane; i < Dd/4; i += 32){
    float4 xv = xr[i];
    #pragma unroll
    for (int e = 0; e < Ee; e++){
      float4 wv = ((const float4*)(Wr + (size_t)e*Dd))[i];
      acc[e] += xv.x*wv.x + xv.y*wv.y + xv.z*wv.z + xv.w*wv.w;
    }
  }
  #pragma unroll
  for (int e = 0; e < Ee; e++){
    #pragma unroll
    for (int o = 16; o > 0; o >>= 1) acc[e] += __shfl_xor_sync(0xffffffffu, acc[e], o);
  }
  if (lane == 0){
    float lg[Ee];
    #pragma unroll
    for (int e = 0; e < Ee; e++) lg[e] = acc[e] + br[e];
    // top-2, earliest-index tie-break (matches jax.lax.top_k stable descending)
    int i0 = 0;
    #pragma unroll
    for (int e = 1; e < Ee; e++) if (lg[e] > lg[i0]) i0 = e;
    int i1 = (i0 == 0) ? 1 : 0;
    #pragma unroll
    for (int e = 0; e < Ee; e++) if (e != i0 && lg[e] > lg[i1]) i1 = e;
    float ev = expf(lg[i1] - lg[i0]);
    float g0 = 1.f / (1.f + ev);
    float g1 = ev / (1.f + ev);
    int p0 = atomicAdd(&d_cnt[i0], 1);
    int p1 = atomicAdd(&d_cnt[i1], 1);
    d_expert[2*t]   = i0; d_pos[2*t]   = p0; d_gatev[2*t]   = g0;
    d_expert[2*t+1] = i1; d_pos[2*t+1] = p1; d_gatev[2*t+1] = g1;
  }
}

__global__ void scan_kernel(){
  if (threadIdx.x == 0){
    int s = 0;
    #pragma unroll
    for (int e = 0; e < Ee; e++){ d_off[e] = s; s += d_cnt[e]; }
  }
}

__global__ void scatter_kernel(const float* __restrict__ x){
  int slot = blockIdx.x;       // t*2 + k
  int t = slot >> 1;
  int e = d_expert[slot];
  int row = d_off[e] + d_pos[slot];
  if (threadIdx.x == 0) d_rowof[slot] = row;
  float4 v = ((const float4*)(x + (size_t)t*Dd))[threadIdx.x];
  ((float4*)(d_xp + (size_t)row*Dd))[threadIdx.x] = v;
}

// ---------------- grouped GEMM (tf32 mma.sync), BM=BN=128, BK=16 ----------------
// A: [rows, KDIM] row-major (expert segment), B: per-expert [KDIM, NDIM] row-major.
// C[m,n] = sum_k A[m,k]*B[k,n] + bias[n], optional exact GELU.
template<int KDIM, int NDIM, bool DOGELU>
__global__ __launch_bounds__(256, 2)
void gemm_kernel(const float* __restrict__ Aall, const float* __restrict__ Ball,
                 const float* __restrict__ bias, float* __restrict__ Call){
  constexpr int BK = 16;
  constexpr int NK = KDIM / BK;
  __shared__ float sA[2][128 * 20];   // row stride 20 -> conflict-free frag loads
  __shared__ float sB[2][16 * 136];   // row stride 136 -> conflict-free frag loads

  int e = blockIdx.z;
  int cnt = d_cnt[e];
  int tm = blockIdx.y;
  if (tm * 128 >= cnt) return;        // uniform early-exit for over-provisioned grid
  int off = d_off[e];
  int tn = blockIdx.x;

  const float* A = Aall + ((size_t)off + (size_t)tm * 128) * KDIM;
  const float* B = Ball + (size_t)e * KDIM * NDIM + tn * 128;
  int tid = threadIdx.x;

  // ---- async stage loader ----
  auto load_stage = [&](int ks, int buf){
    const float* Ak = A + ks * BK;
    const float* Bk = B + (size_t)ks * BK * NDIM;
    #pragma unroll
    for (int i = tid; i < 512; i += 256){        // A: 128x16 floats = 512 float4
      int r = i >> 2, kc = i & 3;
      cp16(&sA[buf][r * 20 + kc * 4], Ak + (size_t)r * KDIM + kc * 4);
    }
    #pragma unroll
    for (int i = tid; i < 512; i += 256){        // B: 16x128 floats = 512 float4
      int k = i >> 5, nc = i & 31;
      cp16(&sB[buf][k * 136 + nc * 4], Bk + (size_t)k * NDIM + nc * 4);
    }
    cp_commit();
  };

  int warp = tid >> 5, lane = tid & 31;
  int wm = (warp & 3) * 32;            // 4 warps along M
  int wn = (warp >> 2) * 64;           // 2 warps along N
  int g = lane >> 2, tg = lane & 3;

  float acc[2][8][4];
  #pragma unroll
  for (int mt = 0; mt < 2; mt++)
    #pragma unroll
    for (int nt = 0; nt < 8; nt++)
      #pragma unroll
      for (int q = 0; q < 4; q++) acc[mt][nt][q] = 0.f;

  load_stage(0, 0);

  #pragma unroll 1
  for (int ks = 0; ks < NK; ks++){
    int buf = ks & 1;
    if (ks + 1 < NK) load_stage(ks + 1, buf ^ 1);
    if (ks + 1 < NK) cp_wait1(); else cp_wait0();
    __syncthreads();

    const float* a = sA[buf];
    const float* b = sB[buf];
    #pragma unroll
    for (int kk = 0; kk < 2; kk++){
      unsigned af[2][4], bf[8][2];
      int k0 = kk * 8 + tg;
      #pragma unroll
      for (int mt = 0; mt < 2; mt++){
        int r = wm + mt * 16 + g;
        af[mt][0] = f2tf32(a[r * 20 + k0]);
        af[mt][1] = f2tf32(a[(r + 8) * 20 + k0]);
        af[mt][2] = f2tf32(a[r * 20 + k0 + 4]);
        af[mt][3] = f2tf32(a[(r + 8) * 20 + k0 + 4]);
      }
      #pragma unroll
      for (int nt = 0; nt < 8; nt++){
        int c = wn + nt * 8 + g;
        bf[nt][0] = f2tf32(b[(kk * 8 + tg) * 136 + c]);
        bf[nt][1] = f2tf32(b[(kk * 8 + tg + 4) * 136 + c]);
      }
      #pragma unroll
      for (int mt = 0; mt < 2; mt++)
        #pragma unroll
        for (int nt = 0; nt < 8; nt++)
          mma_tf32(acc[mt][nt], af[mt], bf[nt]);
    }
    __syncthreads();
  }

  // ---- epilogue: bias (+gelu), guarded store ----
  float* Crow = Call + ((size_t)off + (size_t)tm * 128) * NDIM + tn * 128;
  #pragma unroll
  for (int mt = 0; mt < 2; mt++){
    #pragma unroll
    for (int nt = 0; nt < 8; nt++){
      int r = wm + mt * 16 + g;
      int c = wn + nt * 8 + tg * 2;
      float2 bb = *(const float2*)&bias[(size_t)e * NDIM + tn * 128 + c];
      float v0 = acc[mt][nt][0] + bb.x;
      float v1 = acc[mt][nt][1] + bb.y;
      float v2 = acc[mt][nt][2] + bb.x;
      float v3 = acc[mt][nt][3] + bb.y;
      if (DOGELU){
        v0 = gelu_exact(v0); v1 = gelu_exact(v1);
        v2 = gelu_exact(v2); v3 = gelu_exact(v3);
      }
      if (tm * 128 + r < cnt){
        float2 o; o.x = v0; o.y = v1;
        *(float2*)&Crow[(size_t)r * NDIM + c] = o;
      }
      if (tm * 128 + r + 8 < cnt){
        float2 o; o.x = v2; o.y = v3;
        *(float2*)&Crow[(size_t)(r + 8) * NDIM + c] = o;
      }
    }
  }
}

// ---------------- combine ----------------
__global__ void combine_kernel(float* __restrict__ out){
  int t = blockIdx.x;
  int r0 = d_rowof[2*t], r1 = d_rowof[2*t+1];
  float g0 = d_gatev[2*t], g1 = d_gatev[2*t+1];
  float4 a = ((const float4*)(d_y + (size_t)r0 * Dd))[threadIdx.x];
  float4 b = ((const float4*)(d_y + (size_t)r1 * Dd))[threadIdx.x];
  float4 o;
  o.x = g0*a.x + g1*b.x;
  o.y = g0*a.y + g1*b.y;
  o.z = g0*a.z + g1*b.z;
  o.w = g0*a.w + g1*b.w;
  ((float4*)(out + (size_t)t * Dd))[threadIdx.x] = o;
}

// ---------------- launch ----------------
extern "C" void kernel_launch(void* const* d_in, const int* in_sizes, int n_in,
                              void* d_out, int out_size){
  const float* x  = (const float*)d_in[0];
  const float* Wr = (const float*)d_in[1];
  const float* br = (const float*)d_in[2];
  const float* W1 = (const float*)d_in[3];
  const float* b1 = (const float*)d_in[4];
  const float* W2 = (const float*)d_in[5];
  const float* b2 = (const float*)d_in[6];
  float* out = (float*)d_out;
  (void)in_sizes; (void)n_in; (void)out_size;

  zero_cnt_kernel<<<1, 32>>>();
  router_kernel<<<Tn/8, 256>>>(x, Wr, br);
  scan_kernel<<<1, 32>>>();
  scatter_kernel<<<NROWS, 256>>>(x);

  float* xp = nullptr; float* h = nullptr; float* y = nullptr;
  // use symbols directly via kernels; pass base pointers via device-symbol address at launch
  // (template kernels read/write the __device__ arrays through the passed pointers)
  cudaGetSymbolAddress((void**)&xp, d_xp);
  cudaGetSymbolAddress((void**)&h,  d_h);
  cudaGetSymbolAddress((void**)&y,  d_y);

  // GEMM1: h = gelu(xp @ W1[e] + b1[e]),  K=1024 -> N=4096
  gemm_kernel<Dd, Ii, true ><<<dim3(Ii/128, 64, Ee), 256>>>(xp, W1, b1, h);
  // GEMM2: y = h @ W2[e] + b2[e],         K=4096 -> N=1024
  gemm_kernel<Ii, Dd, false><<<dim3(Dd/128, 64, Ee), 256>>>(h, W2, b2, y);

  combine_kernel<<<Tn, 256>>>(out);
}